// round 4
// baseline (speedup 1.0000x reference)
#include <cuda_runtime.h>
#include <math.h>

// LogSparseAttention: B=2, L=S=2048, H=8, E=D=64.
// Mask: row l<22 -> cols 0..l ; row l>=22 -> {l-10..l} U {l-10-2^i, i=0..10, >=0}.
// <=22 keys/query. Gather attention, line-coalesced loads.
// R4: per-lane col table + SHFL lookup (kills 17 inlined col_of), packed f32x2
//     FMA for dots & V accumulation, q loaded direct from global (no smem).

#define BB 2
#define LL 2048
#define HH 8
#define EE 64
#define DD 64
#define QSCALE 0.125f
#define FULL 0xffffffffu

typedef unsigned long long u64;

__device__ __forceinline__ u64 fma2(u64 a, u64 b, u64 c) {
    u64 r; asm("fma.rn.f32x2 %0, %1, %2, %3;" : "=l"(r) : "l"(a), "l"(b), "l"(c));
    return r;
}
__device__ __forceinline__ u64 mul2(u64 a, u64 b) {
    u64 r; asm("mul.rn.f32x2 %0, %1, %2;" : "=l"(r) : "l"(a), "l"(b));
    return r;
}
__device__ __forceinline__ u64 pack2(float x, float y) {
    u64 r; asm("mov.b64 %0, {%1, %2};" : "=l"(r) : "f"(x), "f"(y));
    return r;
}
__device__ __forceinline__ void unpack2(u64 v, float& x, float& y) {
    asm("mov.b64 {%0, %1}, %2;" : "=f"(x), "=f"(y) : "l"(v));
}

__global__ __launch_bounds__(256, 4)
void logsparse_attn_kernel(const float* __restrict__ Q,
                           const float* __restrict__ K,
                           const float* __restrict__ V,
                           float* __restrict__ O)
{
    const int warp = threadIdx.x >> 5;
    const int lane = threadIdx.x & 31;
    const int row  = blockIdx.x * 8 + warp;      // (b*L + l)*H + h
    const int b    = row / (LL * HH);
    const int rem  = row - b * (LL * HH);
    const int l    = rem / HH;
    const int h    = rem - l * HH;

    // ---- per-lane column table: lane j holds col_j / act_j (computed ONCE) ----
    int col; bool act;
    if (l < 22) {
        act = (lane <= l);
        col = act ? lane : 0;
    } else if (lane <= 10) {
        int c = l - 10 - (1 << (10 - lane));
        act = (c >= 0);
        col = act ? c : 0;
    } else if (lane <= 21) {
        act = true;
        col = l - 21 + lane;
    } else {
        act = false; col = 0;
    }

    // ---- q: direct broadcast load from global (1 line per LDG), pre-scaled ----
    const int sub = lane & 7;                    // 16B chunk index within 128B line
    const u64 qs = pack2(QSCALE, QSCALE);
    const ulonglong2* qp = (const ulonglong2*)(Q + row * EE);
    ulonglong2 qa = qp[sub];                     // dims sub*4 .. sub*4+3
    ulonglong2 qb = qp[8 + sub];                 // dims 32+sub*4 ..
    qa.x = mul2(qa.x, qs); qa.y = mul2(qa.y, qs);
    qb.x = mul2(qb.x, qs); qb.y = mul2(qb.y, qs);

    const float* Kbh = K + (b * (LL * HH) + h) * EE;
    const float* Vbh = V + (b * (LL * HH) + h) * DD;

    // ---- score phase: 8 lanes/key, 4 keys/iter, 6 iters (covers 24 slots) ----
    const int grp = lane >> 3;
    float s = -INFINITY;
#pragma unroll
    for (int jb = 0; jb < 6; ++jb) {
        int cj = __shfl_sync(FULL, col, jb * 4 + grp);
        const ulonglong2* kp = (const ulonglong2*)(Kbh + cj * (HH * EE));
        ulonglong2 ka = kp[sub];
        ulonglong2 kb = kp[8 + sub];
        u64 a2 = mul2(qa.x, ka.x);
        a2 = fma2(qa.y, ka.y, a2);
        a2 = fma2(qb.x, kb.x, a2);
        a2 = fma2(qb.y, kb.y, a2);
        float px, py; unpack2(a2, px, py);
        float part = px + py;
        part += __shfl_xor_sync(FULL, part, 1);
        part += __shfl_xor_sync(FULL, part, 2);
        part += __shfl_xor_sync(FULL, part, 4);   // all 8 lanes of group hold s_j
        float v = __shfl_sync(FULL, part, (lane & 3) << 3);
        if ((lane >> 2) == jb) s = v;             // lane j holds s_j
    }
    if (!act) s = -INFINITY;

    // ---- prefetch all V rows (independent of softmax; hidden by shuffles) ----
    const int kp2 = lane >> 4;                    // key parity within pair
    const int dl  = lane & 15;                    // 16B chunk of 64-dim row
    ulonglong2 vv[11];
#pragma unroll
    for (int it = 0; it < 11; ++it) {
        int cj = __shfl_sync(FULL, col, it * 2 + kp2);
        vv[it] = ((const ulonglong2*)(Vbh + cj * (HH * DD)))[dl];
    }

    // ---- warp softmax over <=22 slots ----
    float m = s;
#pragma unroll
    for (int o = 16; o; o >>= 1) m = fmaxf(m, __shfl_xor_sync(FULL, m, o));
    float p = __expf(s - m);                      // -inf -> 0
    float sum = p;
#pragma unroll
    for (int o = 16; o; o >>= 1) sum += __shfl_xor_sync(FULL, sum, o);
    p *= __frcp_rn(sum);

    // ---- weighted accumulation (packed) ----
    u64 acc0 = pack2(0.f, 0.f), acc1 = acc0;
#pragma unroll
    for (int it = 0; it < 11; ++it) {
        float pj = __shfl_sync(FULL, p, it * 2 + kp2);
        u64 pj2 = pack2(pj, pj);
        acc0 = fma2(pj2, vv[it].x, acc0);
        acc1 = fma2(pj2, vv[it].y, acc1);
    }
    float a0, a1, a2f, a3;
    unpack2(acc0, a0, a1);
    unpack2(acc1, a2f, a3);
    a0  += __shfl_xor_sync(FULL, a0,  16);        // combine even/odd key halves
    a1  += __shfl_xor_sync(FULL, a1,  16);
    a2f += __shfl_xor_sync(FULL, a2f, 16);
    a3  += __shfl_xor_sync(FULL, a3,  16);

    if (lane < 16)
        ((float4*)(O + row * DD))[dl] = make_float4(a0, a1, a2f, a3);
}

extern "C" void kernel_launch(void* const* d_in, const int* in_sizes, int n_in,
                              void* d_out, int out_size) {
    const float* Q = (const float*)d_in[0];
    const float* K = (const float*)d_in[1];
    const float* V = (const float*)d_in[2];
    float* O = (float*)d_out;

    const int total_rows = BB * LL * HH;   // 32768 warps
    dim3 grid(total_rows / 8);
    logsparse_attn_kernel<<<grid, 256>>>(Q, K, V, O);
}

// round 5
// speedup vs baseline: 1.0156x; 1.0156x over previous
#include <cuda_runtime.h>
#include <math.h>

// LogSparseAttention: B=2, L=S=2048, H=8, E=D=64.
// Mask: row l<22 -> cols 0..l ; row l>=22 -> {l-10..l} U {l-10-2^i, i=0..10, >=0}.
// <=22 keys/query -> gather attention, line-coalesced loads.
// R5: block = 8 CONSECUTIVE l of same (b,h)  => gathered K/V lines overlap ~4x
//     across warps -> L1 hits instead of L2 (234cyc -> 39cyc). Inline ALU col
//     computation (no SHFL in load loops), packed f32x2 FMA, direct q load.

#define BB 2
#define LL 2048
#define HH 8
#define EE 64
#define DD 64
#define QSCALE 0.125f
#define FULL 0xffffffffu

typedef unsigned long long u64;

__device__ __forceinline__ u64 fma2(u64 a, u64 b, u64 c) {
    u64 r; asm("fma.rn.f32x2 %0, %1, %2, %3;" : "=l"(r) : "l"(a), "l"(b), "l"(c));
    return r;
}
__device__ __forceinline__ u64 mul2(u64 a, u64 b) {
    u64 r; asm("mul.rn.f32x2 %0, %1, %2;" : "=l"(r) : "l"(a), "l"(b));
    return r;
}
__device__ __forceinline__ u64 pack2(float x, float y) {
    u64 r; asm("mov.b64 %0, {%1, %2};" : "=l"(r) : "f"(x), "f"(y));
    return r;
}
__device__ __forceinline__ void unpack2(u64 v, float& x, float& y) {
    asm("mov.b64 {%0, %1}, %2;" : "=f"(x), "=f"(y) : "l"(v));
}

// Clamped column for key slot j of query row l (>=0 even when inactive).
__device__ __forceinline__ int col_of(int l, int j) {
    int c;
    if (l < 22) {
        c = (j <= l) ? j : 0;
    } else if (j <= 10) {
        c = l - 10 - (1 << ((10 - j) & 31));
        c = (c >= 0) ? c : 0;
    } else if (j <= 21) {
        c = l - 21 + j;
    } else {
        c = 0;
    }
    return c;
}

__device__ __forceinline__ bool act_of(int l, int j) {
    if (j > 21) return false;
    if (l < 22) return j <= l;
    if (j <= 10) return (l - 10 - (1 << ((10 - j) & 31))) >= 0;
    return true;
}

__global__ __launch_bounds__(256, 4)
void logsparse_attn_kernel(const float* __restrict__ Q,
                           const float* __restrict__ K,
                           const float* __restrict__ V,
                           float* __restrict__ O)
{
    const int warp = threadIdx.x >> 5;
    const int lane = threadIdx.x & 31;

    // gid ordered (b, h, l): 8 warps of a block = 8 consecutive l, same (b,h).
    const int gid = blockIdx.x * 8 + warp;
    const int l   = gid & (LL - 1);
    const int bh  = gid >> 11;                   // b*H + h
    const int h   = bh & (HH - 1);
    const int b   = bh >> 3;

    const int qoff = ((b * LL + l) * HH + h) * EE;   // Q/O row offset (B,L,H,E)

    // ---- q: broadcast load from global, pre-scaled (packed) ----
    const int sub = lane & 7;                    // 16B chunk within 128B line
    const u64 qs = pack2(QSCALE, QSCALE);
    const ulonglong2* qp = (const ulonglong2*)(Q + qoff);
    ulonglong2 qa = qp[sub];
    ulonglong2 qb = qp[8 + sub];
    qa.x = mul2(qa.x, qs); qa.y = mul2(qa.y, qs);
    qb.x = mul2(qb.x, qs); qb.y = mul2(qb.y, qs);

    const float* Kbh = K + (b * (LL * HH) + h) * EE;
    const float* Vbh = V + (b * (LL * HH) + h) * DD;

    // ---- score phase: 8 lanes/key, 4 keys/iter, 6 iters (24 >= 22 slots) ----
    const int grp = lane >> 3;
    float s = -INFINITY;
#pragma unroll
    for (int jb = 0; jb < 6; ++jb) {
        int cj = col_of(l, jb * 4 + grp);
        const ulonglong2* kp = (const ulonglong2*)(Kbh + cj * (HH * EE));
        ulonglong2 ka = kp[sub];
        ulonglong2 kb = kp[8 + sub];
        u64 a2 = mul2(qa.x, ka.x);
        a2 = fma2(qa.y, ka.y, a2);
        a2 = fma2(qb.x, kb.x, a2);
        a2 = fma2(qb.y, kb.y, a2);
        float px, py; unpack2(a2, px, py);
        float part = px + py;
        part += __shfl_xor_sync(FULL, part, 1);
        part += __shfl_xor_sync(FULL, part, 2);
        part += __shfl_xor_sync(FULL, part, 4);
        float v = __shfl_sync(FULL, part, (lane & 3) << 3);
        if ((lane >> 2) == jb) s = v;            // lane j holds s_j
    }
    if (!act_of(l, lane)) s = -INFINITY;

    // ---- prefetch all V rows (independent of softmax) ----
    const int kp2 = lane >> 4;                   // key parity within pair
    const int dl  = lane & 15;                   // 16B chunk of 64-dim row
    ulonglong2 vv[11];
#pragma unroll
    for (int it = 0; it < 11; ++it) {
        int cj = col_of(l, it * 2 + kp2);
        vv[it] = ((const ulonglong2*)(Vbh + cj * (HH * DD)))[dl];
    }

    // ---- warp softmax over <=22 slots (hides V loads) ----
    float m = s;
#pragma unroll
    for (int o = 16; o; o >>= 1) m = fmaxf(m, __shfl_xor_sync(FULL, m, o));
    float p = __expf(s - m);                     // -inf -> 0
    float sum = p;
#pragma unroll
    for (int o = 16; o; o >>= 1) sum += __shfl_xor_sync(FULL, sum, o);
    p *= __frcp_rn(sum);

    // ---- weighted accumulation (packed) ----
    u64 acc0 = pack2(0.f, 0.f), acc1 = acc0;
#pragma unroll
    for (int it = 0; it < 11; ++it) {
        float pj = __shfl_sync(FULL, p, it * 2 + kp2);
        u64 pj2 = pack2(pj, pj);
        acc0 = fma2(pj2, vv[it].x, acc0);
        acc1 = fma2(pj2, vv[it].y, acc1);
    }
    float a0, a1, a2f, a3;
    unpack2(acc0, a0, a1);
    unpack2(acc1, a2f, a3);
    a0  += __shfl_xor_sync(FULL, a0,  16);       // combine even/odd key halves
    a1  += __shfl_xor_sync(FULL, a1,  16);
    a2f += __shfl_xor_sync(FULL, a2f, 16);
    a3  += __shfl_xor_sync(FULL, a3,  16);

    if (lane < 16)
        ((float4*)(O + qoff))[dl] = make_float4(a0, a1, a2f, a3);
}

extern "C" void kernel_launch(void* const* d_in, const int* in_sizes, int n_in,
                              void* d_out, int out_size) {
    const float* Q = (const float*)d_in[0];
    const float* K = (const float*)d_in[1];
    const float* V = (const float*)d_in[2];
    float* O = (float*)d_out;

    const int total_rows = BB * LL * HH;   // 32768 warps
    dim3 grid(total_rows / 8);
    logsparse_attn_kernel<<<grid, 256>>>(Q, K, V, O);
}

// round 6
// speedup vs baseline: 1.1780x; 1.1599x over previous
#include <cuda_runtime.h>
#include <math.h>

// LogSparseAttention: B=2, L=S=2048, H=8, E=D=64.
// Mask: row l<22 -> cols 0..l ; row l>=22 -> {l-10..l} U {l-10-2^i, i=0..10, >=0}.
// R6: 4 query rows per warp (8-lane group per row). The 4 rows' local windows
//     union to 14 contiguous columns -> each window K/V line is loaded ONCE per
//     warp as a single-line broadcast LDG (1.0 cyc/wf instead of 2.07 replay)
//     and reused by all 4 rows. Log-term columns stay row-private.

#define BB 2
#define LL 2048
#define HH 8
#define EE 64
#define DD 64
#define QSCALE 0.125f
#define FULL 0xffffffffu
#define KSTRIDE (HH * EE)      // 512 floats between consecutive K (or V) rows of same (b,h)

typedef unsigned long long u64;

__device__ __forceinline__ u64 fma2(u64 a, u64 b, u64 c) {
    u64 r; asm("fma.rn.f32x2 %0, %1, %2, %3;" : "=l"(r) : "l"(a), "l"(b), "l"(c));
    return r;
}
__device__ __forceinline__ u64 mul2(u64 a, u64 b) {
    u64 r; asm("mul.rn.f32x2 %0, %1, %2;" : "=l"(r) : "l"(a), "l"(b));
    return r;
}
__device__ __forceinline__ u64 pack2(float x, float y) {
    u64 r; asm("mov.b64 %0, {%1, %2};" : "=l"(r) : "f"(x), "f"(y));
    return r;
}
__device__ __forceinline__ void unpack2(u64 v, float& x, float& y) {
    asm("mov.b64 {%0, %1}, %2;" : "=f"(x), "=f"(y) : "l"(v));
}

__global__ __launch_bounds__(256, 4)
void logsparse_attn_kernel(const float* __restrict__ Q,
                           const float* __restrict__ K,
                           const float* __restrict__ V,
                           float* __restrict__ O)
{
    const int warp = threadIdx.x >> 5;
    const int lane = threadIdx.x & 31;
    const int sub  = lane & 7;          // chunk within row (16B units)
    const int lanebase = lane & 24;     // first lane of this 8-lane group

    const int gid   = blockIdx.x * 8 + warp;     // warp id over 8192
    const int lbase = (gid & 511) << 2;          // 512 warps per (b,h); 4 rows each
    const int bh    = gid >> 9;                  // b*H + h
    const int h     = bh & (HH - 1);
    const int b     = bh >> 3;
    const int l     = lbase + (lane >> 3);       // this group's query row
    const bool causal = (l < 22);

    const float* Kbh = K + (b * (LL * HH) + h) * EE;
    const float* Vbh = V + (b * (LL * HH) + h) * DD;

    // ---- q for own row, pre-scaled, packed ----
    const int qoff = ((b * LL + l) * HH + h) * EE;
    const ulonglong2* qp = (const ulonglong2*)(Q + qoff);
    ulonglong2 qa = qp[sub];
    ulonglong2 qb = qp[8 + sub];
    const u64 qs = pack2(QSCALE, QSCALE);
    qa.x = mul2(qa.x, qs); qa.y = mul2(qa.y, qs);
    qb.x = mul2(qb.x, qs); qb.y = mul2(qb.y, qs);

    // scores: lane holds slots {sub, sub+8, sub+16} of its row
    float s0 = -INFINITY, s1 = -INFINITY, s2 = -INFINITY;

    // ---- window scores: shared cols c = lbase-10 .. lbase+3 (broadcast loads) ----
#pragma unroll
    for (int t = 0; t < 14; ++t) {
        int c  = lbase - 10 + t;
        int cc = (c < 0) ? 0 : c;
        const ulonglong2* kp = (const ulonglong2*)(Kbh + cc * KSTRIDE);
        ulonglong2 ka = kp[sub];          // all 32 lanes in line0 of K[cc]
        ulonglong2 kb = kp[8 + sub];      // line1
        int  j   = causal ? c : (c - l + 21);
        bool act = (c >= 0) && (causal ? (c <= l) : (j >= 11 && j <= 21));
        u64 d = mul2(qa.x, ka.x);
        d = fma2(qa.y, ka.y, d);
        d = fma2(qb.x, kb.x, d);
        d = fma2(qb.y, kb.y, d);
        float px, py; unpack2(d, px, py);
        float part = px + py;
        part += __shfl_xor_sync(FULL, part, 1);
        part += __shfl_xor_sync(FULL, part, 2);
        part += __shfl_xor_sync(FULL, part, 4);
        if (act && sub == (j & 7)) {
            int jr = j >> 3;
            if (jr == 0) s0 = part; else if (jr == 1) s1 = part; else s2 = part;
        }
    }

    // ---- log scores: slots j = 10-i, row-private cols ----
#pragma unroll
    for (int i = 0; i < 11; ++i) {
        const int j = 10 - i;
        int c; bool act;
        if (causal) { act = (j <= l); c = act ? j : 0; }
        else        { c = l - 10 - (1 << i); act = (c >= 0); c = act ? c : 0; }
        const ulonglong2* kp = (const ulonglong2*)(Kbh + c * KSTRIDE);
        ulonglong2 ka = kp[sub];
        ulonglong2 kb = kp[8 + sub];
        u64 d = mul2(qa.x, ka.x);
        d = fma2(qa.y, ka.y, d);
        d = fma2(qb.x, kb.x, d);
        d = fma2(qb.y, kb.y, d);
        float px, py; unpack2(d, px, py);
        float part = px + py;
        part += __shfl_xor_sync(FULL, part, 1);
        part += __shfl_xor_sync(FULL, part, 2);
        part += __shfl_xor_sync(FULL, part, 4);
        if (act && sub == (j & 7)) {
            if ((j >> 3) == 0) s0 = part; else s1 = part;   // j <= 10
        }
    }

    // ---- per-row softmax (width-8 group reduce) ----
    float m = fmaxf(s0, fmaxf(s1, s2));
    m = fmaxf(m, __shfl_xor_sync(FULL, m, 1));
    m = fmaxf(m, __shfl_xor_sync(FULL, m, 2));
    m = fmaxf(m, __shfl_xor_sync(FULL, m, 4));
    float p0 = __expf(s0 - m), p1 = __expf(s1 - m), p2 = __expf(s2 - m);
    float sum = p0 + p1 + p2;
    sum += __shfl_xor_sync(FULL, sum, 1);
    sum += __shfl_xor_sync(FULL, sum, 2);
    sum += __shfl_xor_sync(FULL, sum, 4);
    float inv = __frcp_rn(sum);
    p0 *= inv; p1 *= inv; p2 *= inv;

    // ---- V accumulation: lane holds dims {sub*4..+3, 32+sub*4..+3} of own row ----
    u64 a00 = pack2(0.f, 0.f), a01 = a00, a10 = a00, a11 = a00;

    // window V (shared cols, broadcast loads; p=0 kills inactive slots)
#pragma unroll
    for (int t = 0; t < 14; ++t) {
        int c  = lbase - 10 + t;
        int cc = (c < 0) ? 0 : c;
        const ulonglong2* vp = (const ulonglong2*)(Vbh + cc * KSTRIDE);
        ulonglong2 va = vp[sub];
        ulonglong2 vb = vp[8 + sub];
        int  j   = causal ? c : (c - l + 21);
        bool act = (c >= 0) && (causal ? (c <= l) : (j >= 11 && j <= 21));
        int  jj  = act ? j : 0;
        int  jr  = jj >> 3;
        float psel = (jr == 0) ? p0 : ((jr == 1) ? p1 : p2);
        float pj = __shfl_sync(FULL, psel, lanebase | (jj & 7));
        pj = act ? pj : 0.0f;
        u64 pj2 = pack2(pj, pj);
        a00 = fma2(pj2, va.x, a00); a01 = fma2(pj2, va.y, a01);
        a10 = fma2(pj2, vb.x, a10); a11 = fma2(pj2, vb.y, a11);
    }

    // log V (row-private cols; causal rows deduped against the window loop)
#pragma unroll
    for (int i = 0; i < 11; ++i) {
        const int j = 10 - i;
        int c; bool act;
        if (causal) { act = (j <= l) && (j < lbase - 10); c = (j <= l) ? j : 0; }
        else        { c = l - 10 - (1 << i); act = (c >= 0); c = act ? c : 0; }
        const ulonglong2* vp = (const ulonglong2*)(Vbh + c * KSTRIDE);
        ulonglong2 va = vp[sub];
        ulonglong2 vb = vp[8 + sub];
        float psel = (j <= 7) ? p0 : p1;
        float pj = __shfl_sync(FULL, psel, lanebase | (j & 7));
        pj = act ? pj : 0.0f;          // inactive slots also have p==0 already
        u64 pj2 = pack2(pj, pj);
        a00 = fma2(pj2, va.x, a00); a01 = fma2(pj2, va.y, a01);
        a10 = fma2(pj2, vb.x, a10); a11 = fma2(pj2, vb.y, a11);
    }

    // ---- store own row ----
    float x0, x1, x2, x3;
    float4* op = (float4*)(O + qoff);
    unpack2(a00, x0, x1); unpack2(a01, x2, x3);
    op[sub] = make_float4(x0, x1, x2, x3);
    unpack2(a10, x0, x1); unpack2(a11, x2, x3);
    op[8 + sub] = make_float4(x0, x1, x2, x3);
}

extern "C" void kernel_launch(void* const* d_in, const int* in_sizes, int n_in,
                              void* d_out, int out_size) {
    const float* Q = (const float*)d_in[0];
    const float* K = (const float*)d_in[1];
    const float* V = (const float*)d_in[2];
    float* O = (float*)d_out;

    // 8192 warps (4 rows each), 8 warps per block -> 1024 blocks.
    dim3 grid(BB * HH * (LL / 4) / 8);
    logsparse_attn_kernel<<<grid, 256>>>(Q, K, V, O);
}